// round 2
// baseline (speedup 1.0000x reference)
#include <cuda_runtime.h>
#include <cuda_bf16.h>

#define N_NODES 100000
#define N_EDGES 1600000
#define D 64
#define D4 16  // D/4

// ---------------- scratch (device globals; no allocation allowed) ------------
__device__ __align__(16) float g_deg[N_NODES];
__device__ __align__(16) float g_dinv[N_NODES];
__device__ __align__(16) int   g_src[N_EDGES];
__device__ __align__(16) int   g_dst[N_EDGES];
__device__ __align__(16) float g_c[N_EDGES];
__device__ __align__(16) float g_h1[N_NODES * D];
__device__ __align__(16) float g_h2[N_NODES * D];
__device__ int g_is64;  // 1 if edge_index is int64, 0 if int32

// ---------------- dtype probe -------------------------------------------------
// If edge_index is truly int64, every value < 2^31 -> high 32-bit word == 0.
// If it is int32 data misread as int64, "high words" are random node ids.
__global__ void k_probe_dtype(const unsigned int* __restrict__ ei_u32) {
    if (threadIdx.x == 0 && blockIdx.x == 0) {
        int is64 = 1;
        for (int i = 0; i < 256; i++) {
            // odd u32 words = high halves of would-be int64 elements
            if (ei_u32[2 * i + 1] != 0u) { is64 = 0; break; }
        }
        g_is64 = is64;
    }
}

// ---------------- degree / norm prep ----------------------------------------
__global__ void k_deg_init() {
    int i = blockIdx.x * blockDim.x + threadIdx.x;
    if (i < N_NODES) g_deg[i] = 1.0f;  // self-loop contributes 1 to in-degree
}

// Read edge list ONCE (dtype-adaptive); compact to int32; accumulate in-degree.
__global__ void k_edge_pass1(const void* __restrict__ eiv) {
    int e = blockIdx.x * blockDim.x + threadIdx.x;
    if (e >= N_EDGES) return;
    int s, d;
    if (g_is64) {
        const long long* ei = (const long long*)eiv;
        s = (int)ei[e];
        d = (int)ei[N_EDGES + e];
    } else {
        const int* ei = (const int*)eiv;
        s = ei[e];
        d = ei[N_EDGES + e];
    }
    g_src[e] = s;
    g_dst[e] = d;
    atomicAdd(&g_deg[d], 1.0f);
}

__global__ void k_dinv() {
    int i = blockIdx.x * blockDim.x + threadIdx.x;
    if (i < N_NODES) g_dinv[i] = rsqrtf(g_deg[i]);  // deg >= 1 always
}

// Per-edge normalization coefficient, computed once, reused by both hops.
__global__ void k_edge_coeff() {
    int e = blockIdx.x * blockDim.x + threadIdx.x;
    if (e >= N_EDGES) return;
    g_c[e] = g_dinv[g_src[e]] * g_dinv[g_dst[e]];
}

// ---------------- propagation hop --------------------------------------------
// h_out[i] = dinv[i]^2 * h_in[i]   (self-loop term; plain stores, pre-scatter)
__global__ void k_hop_init(const float4* __restrict__ in, float4* __restrict__ out) {
    int t = blockIdx.x * blockDim.x + threadIdx.x;
    if (t >= N_NODES * D4) return;
    int node = t >> 4;
    float di = g_dinv[node];
    float c = di * di;
    float4 v = in[t];
    v.x *= c; v.y *= c; v.z *= c; v.w *= c;
    out[t] = v;
}

// 16 threads per edge; each lane moves one float4 of the source row and
// reduces it into the destination row with red.global.add.v4.f32 (sm_90+).
__global__ void k_hop_scatter(const float4* __restrict__ in, float4* __restrict__ out) {
    int t = blockIdx.x * blockDim.x + threadIdx.x;  // up to 25.6M, fits int
    int e = t >> 4;
    if (e >= N_EDGES) return;
    int lane = t & 15;
    int s = g_src[e];
    int d = g_dst[e];
    float c = g_c[e];
    float4 v = __ldg(&in[s * D4 + lane]);
    float4* p = out + d * D4 + lane;
    asm volatile("red.global.add.v4.f32 [%0], {%1, %2, %3, %4};"
                 :: "l"(p), "f"(v.x * c), "f"(v.y * c), "f"(v.z * c), "f"(v.w * c)
                 : "memory");
}

// ---------------- epilogue: out = relu(h @ W^T + b) ---------------------------
// One thread per node; W (64x64 = 16KB) staged in smem, broadcast LDS reads.
__global__ void k_linear_relu(const float* __restrict__ h,
                              const float* __restrict__ W,
                              const float* __restrict__ b,
                              float* __restrict__ out) {
    __shared__ float Ws[D * D];
    __shared__ float bs[D];
    for (int i = threadIdx.x; i < D * D; i += blockDim.x) Ws[i] = W[i];
    if (threadIdx.x < D) bs[threadIdx.x] = b[threadIdx.x];
    __syncthreads();

    int n = blockIdx.x * blockDim.x + threadIdx.x;
    if (n >= N_NODES) return;

    float acc[D];
    #pragma unroll
    for (int o = 0; o < D; o++) acc[o] = bs[o];

    const float4* hr = (const float4*)(h + n * D);
    #pragma unroll
    for (int k4 = 0; k4 < D4; k4++) {
        float4 hv = hr[k4];
        #pragma unroll
        for (int o = 0; o < D; o++) {
            const float* w = &Ws[o * D + k4 * 4];
            acc[o] += hv.x * w[0] + hv.y * w[1] + hv.z * w[2] + hv.w * w[3];
        }
    }
    float* orow = out + n * D;
    #pragma unroll
    for (int o = 0; o < D; o++) orow[o] = fmaxf(acc[o], 0.0f);
}

// ---------------- launch ------------------------------------------------------
extern "C" void kernel_launch(void* const* d_in, const int* in_sizes, int n_in,
                              void* d_out, int out_size) {
    const float* x  = (const float*)d_in[0];   // [N, 64]
    const float* W  = (const float*)d_in[1];   // [64, 64]
    const float* b  = (const float*)d_in[2];   // [64]
    const void*  ei = d_in[3];                 // [2, E] int32 or int64
    float* out = (float*)d_out;                // [N, 64]

    void *h1p = nullptr, *h2p = nullptr;
    cudaGetSymbolAddress(&h1p, g_h1);
    cudaGetSymbolAddress(&h2p, g_h2);
    float4* h1 = (float4*)h1p;
    float4* h2 = (float4*)h2p;

    const int TB = 256;
    const int gN   = (N_NODES + TB - 1) / TB;
    const int gE   = (N_EDGES + TB - 1) / TB;
    const int gNF  = (N_NODES * D4 + TB - 1) / TB;   // node features as float4
    const int gSC  = (N_EDGES * 16 + TB - 1) / TB;   // 16 threads per edge

    // dtype probe + norm prep
    k_probe_dtype<<<1, 32>>>((const unsigned int*)ei);
    k_deg_init   <<<gN, TB>>>();
    k_edge_pass1 <<<gE, TB>>>(ei);
    k_dinv       <<<gN, TB>>>();
    k_edge_coeff <<<gE, TB>>>();

    // hop 1: x -> h1
    k_hop_init   <<<gNF, TB>>>((const float4*)x, h1);
    k_hop_scatter<<<gSC, TB>>>((const float4*)x, h1);

    // hop 2: h1 -> h2
    k_hop_init   <<<gNF, TB>>>((const float4*)h1, h2);
    k_hop_scatter<<<gSC, TB>>>((const float4*)h1, h2);

    // out = relu(h2 @ W^T + b)
    k_linear_relu<<<gN, TB>>>((const float*)h2p, W, b, out);
}

// round 3
// speedup vs baseline: 1.3464x; 1.3464x over previous
#include <cuda_runtime.h>
#include <cuda_bf16.h>

#define N_NODES 100000
#define N_EDGES 1600000
#define D 64
#define SCAN_BLK 256
#define NPART ((N_NODES + SCAN_BLK - 1) / SCAN_BLK)   // 391

// ---------------- scratch (device globals; no allocation allowed) ------------
__device__ __align__(16) int   g_cnt[N_NODES];        // real-edge in-degree
__device__ __align__(16) float g_dinv[N_NODES];
__device__ __align__(16) int   g_src[N_EDGES];
__device__ __align__(16) int   g_dst[N_EDGES];
__device__ __align__(16) int2  g_csr[N_EDGES];        // (src, coeff-as-int), grouped by dst
__device__ __align__(16) int   g_scan[N_NODES];       // inclusive block-local scan
__device__ __align__(16) int   g_part[512];           // per-block partials
__device__ __align__(16) int   g_off[N_NODES];        // CSR row start
__device__ __align__(16) int   g_end[N_NODES];        // CSR row end
__device__ __align__(16) int   g_cursor[N_NODES];     // fill cursors
__device__ __align__(16) float g_h1[N_NODES * D];
__device__ __align__(16) float g_h2[N_NODES * D];
__device__ int g_is64;

// ---------------- dtype probe -------------------------------------------------
// int64 values < 2^31 => high 32-bit words all zero; int32 misread => random.
__global__ void k_probe_dtype(const unsigned int* __restrict__ ei_u32) {
    if (threadIdx.x == 0) {
        int is64 = 1;
        for (int i = 0; i < 256; i++)
            if (ei_u32[2 * i + 1] != 0u) { is64 = 0; break; }
        g_is64 = is64;
    }
}

// ---------------- degree / norm prep ----------------------------------------
__global__ void k_cnt_init() {
    int i = blockIdx.x * blockDim.x + threadIdx.x;
    if (i < N_NODES) g_cnt[i] = 0;
}

// Read edge list ONCE (dtype-adaptive); compact to int32; histogram dst.
__global__ void k_edge_pass1(const void* __restrict__ eiv) {
    int e = blockIdx.x * blockDim.x + threadIdx.x;
    if (e >= N_EDGES) return;
    int s, d;
    if (g_is64) {
        const long long* ei = (const long long*)eiv;
        s = (int)ei[e];
        d = (int)ei[N_EDGES + e];
    } else {
        const int* ei = (const int*)eiv;
        s = ei[e];
        d = ei[N_EDGES + e];
    }
    g_src[e] = s;
    g_dst[e] = d;
    atomicAdd(&g_cnt[d], 1);
}

__global__ void k_dinv() {
    int i = blockIdx.x * blockDim.x + threadIdx.x;
    if (i < N_NODES) g_dinv[i] = rsqrtf((float)(g_cnt[i] + 1));  // +1 self-loop
}

// ---------------- exclusive scan of g_cnt -> CSR offsets ----------------------
__global__ void k_scan_local() {
    __shared__ int s[SCAN_BLK];
    int i = blockIdx.x * SCAN_BLK + threadIdx.x;
    int v = (i < N_NODES) ? g_cnt[i] : 0;
    s[threadIdx.x] = v;
    __syncthreads();
    for (int off = 1; off < SCAN_BLK; off <<= 1) {
        int t = (threadIdx.x >= off) ? s[threadIdx.x - off] : 0;
        __syncthreads();
        s[threadIdx.x] += t;
        __syncthreads();
    }
    if (i < N_NODES) g_scan[i] = s[threadIdx.x];                 // inclusive
    if (threadIdx.x == SCAN_BLK - 1) g_part[blockIdx.x] = s[threadIdx.x];
}

__global__ void k_scan_part() {   // single block of 512 threads, NPART=391
    __shared__ int s[512];
    int v = ((int)threadIdx.x < NPART) ? g_part[threadIdx.x] : 0;
    s[threadIdx.x] = v;
    __syncthreads();
    for (int off = 1; off < 512; off <<= 1) {
        int t = (threadIdx.x >= off) ? s[threadIdx.x - off] : 0;
        __syncthreads();
        s[threadIdx.x] += t;
        __syncthreads();
    }
    if ((int)threadIdx.x < NPART) g_part[threadIdx.x] = s[threadIdx.x];
}

__global__ void k_scan_final() {
    int i = blockIdx.x * SCAN_BLK + threadIdx.x;
    if (i >= N_NODES) return;
    int add  = (blockIdx.x > 0) ? g_part[blockIdx.x - 1] : 0;
    int incl = g_scan[i] + add;
    int excl = incl - g_cnt[i];
    g_off[i]    = excl;
    g_end[i]    = incl;
    g_cursor[i] = excl;
}

// ---------------- CSR fill: (src, coeff) grouped by destination ---------------
__global__ void k_fill() {
    int e = blockIdx.x * blockDim.x + threadIdx.x;
    if (e >= N_EDGES) return;
    int s = g_src[e], d = g_dst[e];
    float c = g_dinv[s] * g_dinv[d];
    int pos = atomicAdd(&g_cursor[d], 1);
    g_csr[pos] = make_int2(s, __float_as_int(c));
}

// ---------------- propagation hop: pure gather, one warp per node -------------
__global__ void k_hop_gather(const float2* __restrict__ in, float2* __restrict__ out) {
    int warp = (blockIdx.x * blockDim.x + threadIdx.x) >> 5;
    if (warp >= N_NODES) return;
    int lane = threadIdx.x & 31;

    int beg = g_off[warp];
    int end = g_end[warp];
    float di = g_dinv[warp];
    float sl = di * di;                       // self-loop coefficient

    float2 acc = __ldg(&in[warp * 32 + lane]);
    acc.x *= sl; acc.y *= sl;

    for (int j = beg; j < end; j += 32) {
        int m = end - j; if (m > 32) m = 32;
        int2 md = make_int2(0, 0);
        if (lane < m) md = __ldg(&g_csr[j + lane]);
        #pragma unroll 4
        for (int i = 0; i < m; i++) {
            int   si = __shfl_sync(0xffffffffu, md.x, i);
            float ci = __int_as_float(__shfl_sync(0xffffffffu, md.y, i));
            float2 v = __ldg(&in[si * 32 + lane]);
            acc.x = fmaf(ci, v.x, acc.x);
            acc.y = fmaf(ci, v.y, acc.y);
        }
    }
    out[warp * 32 + lane] = acc;
}

// ---------------- epilogue: out = relu(h @ W^T + b) ---------------------------
__global__ void k_linear_relu(const float* __restrict__ h,
                              const float* __restrict__ W,
                              const float* __restrict__ b,
                              float* __restrict__ out) {
    __shared__ float Ws[D * D];
    __shared__ float bs[D];
    for (int i = threadIdx.x; i < D * D; i += blockDim.x) Ws[i] = W[i];
    if (threadIdx.x < D) bs[threadIdx.x] = b[threadIdx.x];
    __syncthreads();

    int n = blockIdx.x * blockDim.x + threadIdx.x;
    if (n >= N_NODES) return;

    float acc[D];
    #pragma unroll
    for (int o = 0; o < D; o++) acc[o] = bs[o];

    const float4* hr = (const float4*)(h + n * D);
    #pragma unroll
    for (int k4 = 0; k4 < D / 4; k4++) {
        float4 hv = hr[k4];
        #pragma unroll
        for (int o = 0; o < D; o++) {
            const float* w = &Ws[o * D + k4 * 4];
            acc[o] += hv.x * w[0] + hv.y * w[1] + hv.z * w[2] + hv.w * w[3];
        }
    }
    float* orow = out + n * D;
    #pragma unroll
    for (int o = 0; o < D; o++) orow[o] = fmaxf(acc[o], 0.0f);
}

// ---------------- launch ------------------------------------------------------
extern "C" void kernel_launch(void* const* d_in, const int* in_sizes, int n_in,
                              void* d_out, int out_size) {
    const float* x  = (const float*)d_in[0];   // [N, 64]
    const float* W  = (const float*)d_in[1];   // [64, 64]
    const float* b  = (const float*)d_in[2];   // [64]
    const void*  ei = d_in[3];                 // [2, E] int32 or int64
    float* out = (float*)d_out;                // [N, 64]

    void *h1p = nullptr, *h2p = nullptr;
    cudaGetSymbolAddress(&h1p, g_h1);
    cudaGetSymbolAddress(&h2p, g_h2);

    const int TB = 256;
    const int gN  = (N_NODES + TB - 1) / TB;
    const int gE  = (N_EDGES + TB - 1) / TB;
    const int gH  = (N_NODES * 32 + TB - 1) / TB;   // one warp per node

    // dtype probe + CSR build
    k_probe_dtype<<<1, 32>>>((const unsigned int*)ei);
    k_cnt_init   <<<gN, TB>>>();
    k_edge_pass1 <<<gE, TB>>>(ei);
    k_dinv       <<<gN, TB>>>();
    k_scan_local <<<NPART, SCAN_BLK>>>();
    k_scan_part  <<<1, 512>>>();
    k_scan_final <<<NPART, SCAN_BLK>>>();
    k_fill       <<<gE, TB>>>();

    // two hops: x -> h1 -> h2 (pure gather, no atomics)
    k_hop_gather<<<gH, TB>>>((const float2*)x, (float2*)h1p);
    k_hop_gather<<<gH, TB>>>((const float2*)h1p, (float2*)h2p);

    // out = relu(h2 @ W^T + b)
    k_linear_relu<<<gN, TB>>>((const float*)h2p, W, b, out);
}

// round 4
// speedup vs baseline: 1.3572x; 1.0080x over previous
#include <cuda_runtime.h>
#include <cuda_fp16.h>

#define N_NODES 100000
#define N_EDGES 1600000
#define D 64
#define SCAN_BLK 256
#define NPART ((N_NODES + SCAN_BLK - 1) / SCAN_BLK)   // 391

// ---------------- scratch (device globals; no allocation allowed) ------------
__device__ __align__(16) int     g_cnt[N_NODES];      // real-edge in-degree
__device__ __align__(16) float   g_dinv[N_NODES];
__device__ __align__(16) int2    g_csr[N_EDGES];      // (src, coeff), grouped by dst
__device__ __align__(16) int     g_scan[N_NODES];     // inclusive block-local scan
__device__ __align__(16) int     g_part[512];         // per-block partials
__device__ __align__(16) int     g_off[N_NODES];      // CSR row start
__device__ __align__(16) int     g_end[N_NODES];      // CSR row end
__device__ __align__(16) int     g_cursor[N_NODES];   // fill cursors
__device__ __align__(16) __half2 g_xh [N_NODES * 32]; // x as fp16 (row = 32 half2)
__device__ __align__(16) __half2 g_h1h[N_NODES * 32]; // hop-1 result, fp16
__device__ __align__(16) float   g_h2 [N_NODES * D];  // hop-2 result, fp32
__device__ int g_is64;

// ---------------- dtype-adaptive edge loader ----------------------------------
// int64 values < 2^31 => high 32-bit words all zero; int32 misread => random.
__device__ __forceinline__ void load_edge(const void* __restrict__ eiv, int e,
                                          int& s, int& d) {
    if (g_is64) {
        const long long* p = (const long long*)eiv;
        s = (int)p[e];
        d = (int)p[N_EDGES + e];
    } else {
        const int* p = (const int*)eiv;
        s = p[e];
        d = p[N_EDGES + e];
    }
}

// ---------------- 1: zero counts + dtype probe --------------------------------
__global__ void k_init(const unsigned int* __restrict__ ei_u32) {
    int i = blockIdx.x * blockDim.x + threadIdx.x;
    if (i < N_NODES) g_cnt[i] = 0;
    if (i == 0) {
        int is64 = 1;
        for (int k = 0; k < 256; k++)
            if (ei_u32[2 * k + 1] != 0u) { is64 = 0; break; }
        g_is64 = is64;
    }
}

// ---------------- 2: in-degree histogram --------------------------------------
__global__ void k_pass1(const void* __restrict__ eiv) {
    int e = blockIdx.x * blockDim.x + threadIdx.x;
    if (e >= N_EDGES) return;
    int s, d;
    load_edge(eiv, e, s, d);
    atomicAdd(&g_cnt[d], 1);
}

// ---------------- 3: dinv + block-local inclusive scan ------------------------
__global__ void k_scan_local() {
    __shared__ int s[SCAN_BLK];
    int i = blockIdx.x * SCAN_BLK + threadIdx.x;
    int v = (i < N_NODES) ? g_cnt[i] : 0;
    if (i < N_NODES) g_dinv[i] = rsqrtf((float)(v + 1));   // +1 self-loop
    s[threadIdx.x] = v;
    __syncthreads();
    for (int off = 1; off < SCAN_BLK; off <<= 1) {
        int t = (threadIdx.x >= off) ? s[threadIdx.x - off] : 0;
        __syncthreads();
        s[threadIdx.x] += t;
        __syncthreads();
    }
    if (i < N_NODES) g_scan[i] = s[threadIdx.x];           // inclusive
    if (threadIdx.x == SCAN_BLK - 1) g_part[blockIdx.x] = s[threadIdx.x];
}

// ---------------- 4: scan of per-block partials -------------------------------
__global__ void k_scan_part() {   // single block of 512 threads, NPART=391
    __shared__ int s[512];
    int v = ((int)threadIdx.x < NPART) ? g_part[threadIdx.x] : 0;
    s[threadIdx.x] = v;
    __syncthreads();
    for (int off = 1; off < 512; off <<= 1) {
        int t = (threadIdx.x >= off) ? s[threadIdx.x - off] : 0;
        __syncthreads();
        s[threadIdx.x] += t;
        __syncthreads();
    }
    if ((int)threadIdx.x < NPART) g_part[threadIdx.x] = s[threadIdx.x];
}

// ---------------- 5: scan final + convert x -> fp16 ---------------------------
// Grid covers N_NODES*32 threads; first N_NODES also finish the scan.
__global__ void k_finalize(const float2* __restrict__ x2) {
    int t = blockIdx.x * blockDim.x + threadIdx.x;
    if (t < N_NODES) {
        int p = t >> 8;                                    // SCAN_BLK = 256
        int add  = (p > 0) ? g_part[p - 1] : 0;
        int incl = g_scan[t] + add;
        int excl = incl - g_cnt[t];
        g_off[t]    = excl;
        g_end[t]    = incl;
        g_cursor[t] = excl;
    }
    if (t < N_NODES * 32) {
        float2 v = __ldg(&x2[t]);
        g_xh[t] = __floats2half2_rn(v.x, v.y);
    }
}

// ---------------- 6: CSR fill (src, coeff) grouped by destination -------------
__global__ void k_fill(const void* __restrict__ eiv) {
    int e = blockIdx.x * blockDim.x + threadIdx.x;
    if (e >= N_EDGES) return;
    int s, d;
    load_edge(eiv, e, s, d);
    float c = g_dinv[s] * g_dinv[d];
    int pos = atomicAdd(&g_cursor[d], 1);
    g_csr[pos] = make_int2(s, __float_as_int(c));
}

// ---------------- 7/8: propagation hop (pure gather, fp16 operands) -----------
// One warp per node; lane owns one half2 (2 features). fp32 accumulation.
template <bool OUT_HALF>
__global__ void k_hop(const __half2* __restrict__ in, void* __restrict__ outv) {
    int warp = (blockIdx.x * blockDim.x + threadIdx.x) >> 5;
    if (warp >= N_NODES) return;
    int lane = threadIdx.x & 31;

    int beg = g_off[warp];
    int end = g_end[warp];
    float di = g_dinv[warp];
    float sl = di * di;                         // self-loop coefficient

    float2 hv = __half22float2(__ldg(&in[warp * 32 + lane]));
    float2 acc = make_float2(sl * hv.x, sl * hv.y);

    for (int j = beg; j < end; j += 32) {
        int m = end - j; if (m > 32) m = 32;
        int2 md = make_int2(0, 0);
        if (lane < m) md = __ldg(&g_csr[j + lane]);
        #pragma unroll 4
        for (int i = 0; i < m; i++) {
            int   si = __shfl_sync(0xffffffffu, md.x, i);
            float ci = __int_as_float(__shfl_sync(0xffffffffu, md.y, i));
            float2 v = __half22float2(__ldg(&in[si * 32 + lane]));
            acc.x = fmaf(ci, v.x, acc.x);
            acc.y = fmaf(ci, v.y, acc.y);
        }
    }
    if (OUT_HALF)
        ((__half2*)outv)[warp * 32 + lane] = __floats2half2_rn(acc.x, acc.y);
    else
        ((float2*)outv)[warp * 32 + lane] = acc;
}

// ---------------- 9: out = relu(h2 @ W^T + b) ---------------------------------
__global__ void k_linear_relu(const float* __restrict__ h,
                              const float* __restrict__ W,
                              const float* __restrict__ b,
                              float* __restrict__ out) {
    __shared__ float Ws[D * D];
    __shared__ float bs[D];
    for (int i = threadIdx.x; i < D * D; i += blockDim.x) Ws[i] = W[i];
    if (threadIdx.x < D) bs[threadIdx.x] = b[threadIdx.x];
    __syncthreads();

    int n = blockIdx.x * blockDim.x + threadIdx.x;
    if (n >= N_NODES) return;

    float acc[D];
    #pragma unroll
    for (int o = 0; o < D; o++) acc[o] = bs[o];

    const float4* hr = (const float4*)(h + n * D);
    #pragma unroll
    for (int k4 = 0; k4 < D / 4; k4++) {
        float4 hvv = hr[k4];
        #pragma unroll
        for (int o = 0; o < D; o++) {
            const float* w = &Ws[o * D + k4 * 4];
            acc[o] += hvv.x * w[0] + hvv.y * w[1] + hvv.z * w[2] + hvv.w * w[3];
        }
    }
    float* orow = out + n * D;
    #pragma unroll
    for (int o = 0; o < D; o++) orow[o] = fmaxf(acc[o], 0.0f);
}

// ---------------- launch ------------------------------------------------------
extern "C" void kernel_launch(void* const* d_in, const int* in_sizes, int n_in,
                              void* d_out, int out_size) {
    const float* x  = (const float*)d_in[0];   // [N, 64]
    const float* W  = (const float*)d_in[1];   // [64, 64]
    const float* b  = (const float*)d_in[2];   // [64]
    const void*  ei = d_in[3];                 // [2, E] int32 or int64
    float* out = (float*)d_out;                // [N, 64]

    void *xhp = nullptr, *h1p = nullptr, *h2p = nullptr;
    cudaGetSymbolAddress(&xhp, g_xh);
    cudaGetSymbolAddress(&h1p, g_h1h);
    cudaGetSymbolAddress(&h2p, g_h2);

    const int TB = 256;
    const int gN   = (N_NODES + TB - 1) / TB;
    const int gE   = (N_EDGES + TB - 1) / TB;
    const int gFin = (N_NODES * 32 + TB - 1) / TB;   // finalize+convert threads
    const int gH   = (N_NODES * 32 + TB - 1) / TB;   // one warp per node

    k_init      <<<gN, TB>>>((const unsigned int*)ei);
    k_pass1     <<<gE, TB>>>(ei);
    k_scan_local<<<NPART, SCAN_BLK>>>();
    k_scan_part <<<1, 512>>>();
    k_finalize  <<<gFin, TB>>>((const float2*)x);
    k_fill      <<<gE, TB>>>(ei);

    // two hops: xh -> h1h (fp16) -> h2 (fp32); pure gather, no atomics
    k_hop<true> <<<gH, TB>>>((const __half2*)xhp, h1p);
    k_hop<false><<<gH, TB>>>((const __half2*)h1p, h2p);

    // out = relu(h2 @ W^T + b)
    k_linear_relu<<<gN, TB>>>((const float*)h2p, W, b, out);
}

// round 5
// speedup vs baseline: 1.5114x; 1.1136x over previous
#include <cuda_runtime.h>
#include <cuda_fp16.h>

#define N_NODES 100000
#define N_EDGES 1600000
#define D 64
#define SCAN_BLK 512
#define NPART ((N_NODES + SCAN_BLK - 1) / SCAN_BLK)   // 196

// ---------------- packed f32x2 helpers (sm_103a) ------------------------------
#define PACK2(dst, lo, hi) \
    asm("mov.b64 %0, {%1, %2};" : "=l"(dst) : "f"(lo), "f"(hi))
#define UNPACK2(lo, hi, src) \
    asm("mov.b64 {%0, %1}, %2;" : "=f"(lo), "=f"(hi) : "l"(src))
#define FMA2(acc, a, b) \
    asm("fma.rn.f32x2 %0, %1, %2, %0;" : "+l"(acc) : "l"(a), "l"(b))

// ---------------- scratch (device globals; no allocation allowed) -------------
__device__ __align__(16) int     g_cnt[N_NODES];      // in-degree (re-zeroed each run)
__device__ __align__(16) float   g_dinv[N_NODES];
__device__ __align__(16) int2    g_csr[N_EDGES];      // (src, coeff) grouped by dst
__device__ __align__(16) int     g_off[N_NODES];      // CSR row start
__device__ __align__(16) int     g_end[N_NODES];      // CSR row end
__device__ __align__(16) int     g_cursor[N_NODES];   // fill cursors
__device__ __align__(16) int     g_part[SCAN_BLK];    // per-block scan partials
__device__ __align__(16) __half2 g_xh [N_NODES * 32]; // x as fp16 (row = 32 half2)
__device__ __align__(16) __half2 g_h1h[N_NODES * 32]; // hop-1 result, fp16
__device__ __align__(16) float   g_h2 [N_NODES * D];  // hop-2 result, fp32
__device__ int g_is64;
__device__ int g_ticket;                              // self-resetting

// ---------------- dtype-adaptive edge loader ----------------------------------
__device__ __forceinline__ void load_edge(const void* __restrict__ eiv, int e,
                                          int& s, int& d) {
    if (g_is64) {
        const long long* p = (const long long*)eiv;
        s = (int)p[e];
        d = (int)p[N_EDGES + e];
    } else {
        const int* p = (const int*)eiv;
        s = p[e];
        d = p[N_EDGES + e];
    }
}

// ---------------- 1: zero counts + dtype probe + x -> fp16 --------------------
__global__ void k_init(const unsigned int* __restrict__ ei_u32,
                       const float2* __restrict__ x2) {
    int t = blockIdx.x * blockDim.x + threadIdx.x;
    if (t < N_NODES * 32) {
        float2 v = __ldg(&x2[t]);
        g_xh[t] = __floats2half2_rn(v.x, v.y);
    }
    if (t < N_NODES) g_cnt[t] = 0;
    if (t == 0) {
        int is64 = 1;
        for (int k = 0; k < 256; k++)
            if (ei_u32[2 * k + 1] != 0u) { is64 = 0; break; }
        g_is64 = is64;
    }
}

// ---------------- 2: in-degree histogram --------------------------------------
__global__ void k_pass1(const void* __restrict__ eiv) {
    int e = blockIdx.x * blockDim.x + threadIdx.x;
    if (e >= N_EDGES) return;
    int s, d;
    load_edge(eiv, e, s, d);
    atomicAdd(&g_cnt[d], 1);
}

// ---------------- 3: dinv + block scan + last-block partial scan --------------
__global__ void k_scan_local() {
    __shared__ int s[SCAN_BLK];
    __shared__ int lastFlag;
    int tid = threadIdx.x;
    int i = blockIdx.x * SCAN_BLK + tid;
    int v = (i < N_NODES) ? g_cnt[i] : 0;
    if (i < N_NODES) {
        g_dinv[i] = rsqrtf((float)(v + 1));   // +1 self-loop
        g_cnt[i] = 0;                          // restore for next graph replay
    }
    s[tid] = v;
    __syncthreads();
    for (int off = 1; off < SCAN_BLK; off <<= 1) {
        int t2 = (tid >= off) ? s[tid - off] : 0;
        __syncthreads();
        s[tid] += t2;
        __syncthreads();
    }
    if (i < N_NODES) { g_end[i] = s[tid]; g_off[i] = s[tid] - v; }  // block-local
    if (tid == SCAN_BLK - 1) g_part[blockIdx.x] = s[tid];
    __threadfence();
    if (tid == 0)
        lastFlag = (atomicAdd(&g_ticket, 1) == (int)gridDim.x - 1);
    __syncthreads();
    if (lastFlag) {  // last-arriving block scans the partials
        int p = (tid < NPART) ? *((volatile int*)&g_part[tid]) : 0;
        s[tid] = p;
        __syncthreads();
        for (int off = 1; off < SCAN_BLK; off <<= 1) {
            int t2 = (tid >= off) ? s[tid - off] : 0;
            __syncthreads();
            s[tid] += t2;
            __syncthreads();
        }
        if (tid < NPART) g_part[tid] = s[tid];
        if (tid == 0) g_ticket = 0;            // restore for next replay
    }
}

// ---------------- 4: apply block prefix ---------------------------------------
__global__ void k_finalize() {
    int i = blockIdx.x * blockDim.x + threadIdx.x;
    if (i >= N_NODES) return;
    int p = i >> 9;                            // SCAN_BLK = 512
    int add = (p > 0) ? g_part[p - 1] : 0;
    int excl = g_off[i] + add;
    g_off[i]    = excl;
    g_end[i]   += add;
    g_cursor[i] = excl;
}

// ---------------- 5: CSR fill (src, coeff) grouped by destination -------------
__global__ void k_fill(const void* __restrict__ eiv) {
    int e = blockIdx.x * blockDim.x + threadIdx.x;
    if (e >= N_EDGES) return;
    int s, d;
    load_edge(eiv, e, s, d);
    float c = g_dinv[s] * g_dinv[d];
    int pos = atomicAdd(&g_cursor[d], 1);
    g_csr[pos] = make_int2(s, __float_as_int(c));
}

// ---------------- 6/7: propagation hop: 2 edges in flight per warp ------------
// Lane owns 4 features (uint2 of half2). Lanes 0-15 process even edges,
// lanes 16-31 odd edges; halves combined at the end with shfl_xor(16).
template <bool OUT_HALF>
__global__ void k_hop(const uint2* __restrict__ in, void* __restrict__ outv) {
    int warp = (blockIdx.x * blockDim.x + threadIdx.x) >> 5;
    if (warp >= N_NODES) return;
    int lane = threadIdx.x & 31;
    int fl   = lane & 15;        // float4-slot within row (16 x 8B = 64 half)
    int eh   = lane >> 4;        // which edge of the pair

    int beg = g_off[warp];
    int end = g_end[warp];
    float di = g_dinv[warp];
    float sl = di * di;          // self-loop coefficient

    // self-loop term (only in half 0 so it isn't double counted)
    uint2 rs = __ldg(&in[warp * 16 + fl]);
    float2 s0 = __half22float2(*reinterpret_cast<const __half2*>(&rs.x));
    float2 s1 = __half22float2(*reinterpret_cast<const __half2*>(&rs.y));
    float2 accA = (eh == 0) ? make_float2(sl * s0.x, sl * s0.y) : make_float2(0.f, 0.f);
    float2 accB = (eh == 0) ? make_float2(sl * s1.x, sl * s1.y) : make_float2(0.f, 0.f);

    for (int j = beg; j < end; j += 32) {
        int m = end - j; if (m > 32) m = 32;
        int2 md = make_int2(0, 0);
        if (lane < m) md = __ldg(&g_csr[j + lane]);
        #pragma unroll 4
        for (int i = 0; i < m; i += 2) {
            int idx = i + eh;    // >= m lanes pull md=(0,0) -> ci=0, harmless
            int   si = __shfl_sync(0xffffffffu, md.x, idx);
            float ci = __int_as_float(__shfl_sync(0xffffffffu, md.y, idx));
            uint2 r = __ldg(&in[si * 16 + fl]);
            float2 lo = __half22float2(*reinterpret_cast<const __half2*>(&r.x));
            float2 hi = __half22float2(*reinterpret_cast<const __half2*>(&r.y));
            accA.x = fmaf(ci, lo.x, accA.x);
            accA.y = fmaf(ci, lo.y, accA.y);
            accB.x = fmaf(ci, hi.x, accB.x);
            accB.y = fmaf(ci, hi.y, accB.y);
        }
    }
    // combine edge halves
    accA.x += __shfl_xor_sync(0xffffffffu, accA.x, 16);
    accA.y += __shfl_xor_sync(0xffffffffu, accA.y, 16);
    accB.x += __shfl_xor_sync(0xffffffffu, accB.x, 16);
    accB.y += __shfl_xor_sync(0xffffffffu, accB.y, 16);

    if (eh == 0) {
        if (OUT_HALF) {
            uint2 o;
            *reinterpret_cast<__half2*>(&o.x) = __floats2half2_rn(accA.x, accA.y);
            *reinterpret_cast<__half2*>(&o.y) = __floats2half2_rn(accB.x, accB.y);
            ((uint2*)outv)[warp * 16 + fl] = o;
        } else {
            ((float4*)outv)[warp * 16 + fl] = make_float4(accA.x, accA.y, accB.x, accB.y);
        }
    }
}

// ---------------- 8: out = relu(h2 @ W^T + b), packed f32x2 FMA ---------------
// One thread per node. acc[o] is an f32x2 pair of (even-k, odd-k) partial sums,
// so W pairs come straight out of the row-major smem tile.
__global__ void __launch_bounds__(128) k_linear_relu(
        const float* __restrict__ h, const float* __restrict__ W,
        const float* __restrict__ b, float* __restrict__ out) {
    __shared__ float4 Ws4[D * 16];   // W[o][k] as float4 over k
    __shared__ float bs[D];
    for (int i = threadIdx.x; i < D * 16; i += blockDim.x)
        Ws4[i] = ((const float4*)W)[i];
    for (int i = threadIdx.x; i < D; i += blockDim.x) bs[i] = b[i];
    __syncthreads();

    int n = blockIdx.x * blockDim.x + threadIdx.x;
    if (n >= N_NODES) return;

    unsigned long long acc[D];
    #pragma unroll
    for (int o = 0; o < D; o++) PACK2(acc[o], bs[o], 0.0f);

    const float4* hr = (const float4*)(h + n * D);
    #pragma unroll 2
    for (int k4 = 0; k4 < 16; k4++) {
        float4 hv = hr[k4];
        unsigned long long h01, h23;
        PACK2(h01, hv.x, hv.y);
        PACK2(h23, hv.z, hv.w);
        #pragma unroll
        for (int o = 0; o < D; o++) {
            float4 w = Ws4[o * 16 + k4];
            unsigned long long w01, w23;
            PACK2(w01, w.x, w.y);
            PACK2(w23, w.z, w.w);
            FMA2(acc[o], h01, w01);
            FMA2(acc[o], h23, w23);
        }
    }
    float* orow = out + n * D;
    #pragma unroll
    for (int o = 0; o < D; o++) {
        float lo, hi;
        UNPACK2(lo, hi, acc[o]);
        orow[o] = fmaxf(lo + hi, 0.0f);
    }
}

// ---------------- launch ------------------------------------------------------
extern "C" void kernel_launch(void* const* d_in, const int* in_sizes, int n_in,
                              void* d_out, int out_size) {
    const float* x  = (const float*)d_in[0];   // [N, 64]
    const float* W  = (const float*)d_in[1];   // [64, 64]
    const float* b  = (const float*)d_in[2];   // [64]
    const void*  ei = d_in[3];                 // [2, E] int32 or int64
    float* out = (float*)d_out;                // [N, 64]

    void *xhp = nullptr, *h1p = nullptr, *h2p = nullptr;
    cudaGetSymbolAddress(&xhp, g_xh);
    cudaGetSymbolAddress(&h1p, g_h1h);
    cudaGetSymbolAddress(&h2p, g_h2);

    const int TB = 256;
    const int gBig = (N_NODES * 32 + TB - 1) / TB;   // 3.2M threads
    const int gE   = (N_EDGES + TB - 1) / TB;
    const int gN   = (N_NODES + TB - 1) / TB;
    const int gLin = (N_NODES + 127) / 128;

    k_init      <<<gBig, TB>>>((const unsigned int*)ei, (const float2*)x);
    k_pass1     <<<gE, TB>>>(ei);
    k_scan_local<<<NPART, SCAN_BLK>>>();
    k_finalize  <<<gN, TB>>>();
    k_fill      <<<gE, TB>>>(ei);

    // two hops: xh -> h1h (fp16) -> h2 (fp32); pure gather, no atomics
    k_hop<true> <<<gBig, TB>>>((const uint2*)xhp, h1p);
    k_hop<false><<<gBig, TB>>>((const uint2*)h1p, h2p);

    // out = relu(h2 @ W^T + b)
    k_linear_relu<<<gLin, 128>>>((const float*)h2p, W, b, out);
}